// round 10
// baseline (speedup 1.0000x reference)
#include <cuda_runtime.h>
#include <cuda_bf16.h>
#include <math.h>

// Problem constants
#define B_SZ 8192
#define N_SZ 128
#define D_OWN 16
#define D_GRID 512
#define D_INTR 20
#define H_SZ 128

// Folded-weight + intermediate scratch (device globals: allocation-free)
__device__ float g_Wqk[128 * 128];   // Wq @ Wk^T
__device__ float g_W12[384 * 4];     // W1 @ W2
__device__ float g_Wv12[128 * 4];    // Wv @ W12[128:256]
__device__ float g_b12[4];           // b1 @ W2 + b2
__device__ float g_qk[B_SZ * 128];   // per-batch attention query folded through Wk
__device__ float g_oe4[B_SZ * 4];    // own_e contribution to output
__device__ float g_g4[B_SZ * 4];     // own_grid contribution to output

// ---------------------------------------------------------------------------
// prep1: fold Wqk = Wq @ Wk^T, W12 = W1 @ W2, b12 = b1 @ W2 + b2
// ---------------------------------------------------------------------------
__global__ void prep1_kernel(const float* __restrict__ Wq,
                             const float* __restrict__ Wk,
                             const float* __restrict__ W1,
                             const float* __restrict__ b1,
                             const float* __restrict__ W2,
                             const float* __restrict__ b2) {
    int t = blockIdx.x * blockDim.x + threadIdx.x;
    if (t < 16384) {
        int hp = t >> 7, d = t & 127;
        float acc = 0.f;
        #pragma unroll 8
        for (int h = 0; h < 128; h++) acc += Wq[hp * 128 + h] * Wk[d * 128 + h];
        g_Wqk[t] = acc;  // [hp][d]
    }
    if (t < 1536) {
        int i = t >> 2, o = t & 3;
        float acc = 0.f;
        #pragma unroll 8
        for (int j = 0; j < 128; j++) acc += W1[i * 128 + j] * W2[j * 4 + o];
        g_W12[t] = acc;
    }
    if (t < 4) {
        float acc = b2[t];
        for (int j = 0; j < 128; j++) acc += b1[j] * W2[j * 4 + t];
        g_b12[t] = acc;
    }
}

// ---------------------------------------------------------------------------
// prep2: Wv12 = Wv @ W12[128:256]  (needs g_W12 -> separate launch)
// ---------------------------------------------------------------------------
__global__ void prep2_kernel(const float* __restrict__ Wv) {
    int t = blockIdx.x * blockDim.x + threadIdx.x;
    if (t < 512) {
        int h = t >> 2, o = t & 3;
        float acc = 0.f;
        #pragma unroll 8
        for (int i = 0; i < 128; i++) acc += Wv[h * 128 + i] * g_W12[(128 + i) * 4 + o];
        g_Wv12[t] = acc;
    }
}

// ---------------------------------------------------------------------------
// own path: own_e = relu(state0 @ W_own + b_own)
//           qk[b] = own_e @ Wqk ; oe4[b] = own_e @ W12[0:128]
// 8 batch rows per CTA to amortize Wqk traffic.
// ---------------------------------------------------------------------------
#define OB 8
__global__ void own_kernel(const float* __restrict__ state0,
                           const float* __restrict__ W_own,
                           const float* __restrict__ b_own) {
    __shared__ float s0[OB * 16];
    __shared__ float oe[OB][128];
    int t = threadIdx.x;
    int b0 = blockIdx.x * OB;
    if (t < OB * 16) s0[t] = state0[b0 * 16 + t];
    __syncthreads();
    #pragma unroll
    for (int k = 0; k < 4; k++) {
        int idx = t + k * 256;
        int b = idx >> 7, h = idx & 127;
        float acc = b_own[h];
        #pragma unroll
        for (int d = 0; d < 16; d++) acc += s0[b * 16 + d] * W_own[d * 128 + h];
        oe[b][h] = fmaxf(acc, 0.f);
    }
    __syncthreads();
    // qk: thread (d = t&127, half = t>>7) handles 4 batch rows
    int d = t & 127, g = t >> 7;
    float a0 = 0.f, a1 = 0.f, a2 = 0.f, a3 = 0.f;
    #pragma unroll 4
    for (int h = 0; h < 128; h++) {
        float w = g_Wqk[h * 128 + d];
        a0 += oe[g * 4 + 0][h] * w;
        a1 += oe[g * 4 + 1][h] * w;
        a2 += oe[g * 4 + 2][h] * w;
        a3 += oe[g * 4 + 3][h] * w;
    }
    g_qk[(size_t)(b0 + g * 4 + 0) * 128 + d] = a0;
    g_qk[(size_t)(b0 + g * 4 + 1) * 128 + d] = a1;
    g_qk[(size_t)(b0 + g * 4 + 2) * 128 + d] = a2;
    g_qk[(size_t)(b0 + g * 4 + 3) * 128 + d] = a3;
    if (t < OB * 4) {
        int b = t >> 2, o = t & 3;
        float a = 0.f;
        #pragma unroll 8
        for (int h = 0; h < 128; h++) a += oe[b][h] * g_W12[h * 4 + o];
        g_oe4[(size_t)(b0 + b) * 4 + o] = a;
    }
}

// ---------------------------------------------------------------------------
// grid path: own_grid = relu(state1 @ W_grid + b_grid); g4 = own_grid @ W12[256:384]
// 16 batch rows per CTA so W_grid (256 KB) is streamed 512x not 8192x.
// ---------------------------------------------------------------------------
#define GB 16
__global__ void grid_kernel(const float* __restrict__ state1,
                            const float* __restrict__ W_grid,
                            const float* __restrict__ b_grid) {
    __shared__ float4 s1[GB * 128];   // 16 rows x 512 floats = 32KB
    __shared__ float og[GB][128];
    int t = threadIdx.x;
    int b0 = blockIdx.x * GB;
    const float4* src = (const float4*)(state1 + (size_t)b0 * 512);
    for (int i = t; i < GB * 128; i += 256) s1[i] = src[i];
    __syncthreads();
    int h = t & 127, g = t >> 7;  // each (h, g) handles 8 rows
    float acc[8];
    float bg = b_grid[h];
    #pragma unroll
    for (int k = 0; k < 8; k++) acc[k] = bg;
    for (int dc = 0; dc < 128; dc++) {
        float w0 = W_grid[(4 * dc + 0) * 128 + h];
        float w1 = W_grid[(4 * dc + 1) * 128 + h];
        float w2 = W_grid[(4 * dc + 2) * 128 + h];
        float w3 = W_grid[(4 * dc + 3) * 128 + h];
        #pragma unroll
        for (int k = 0; k < 8; k++) {
            float4 s = s1[(g * 8 + k) * 128 + dc];
            acc[k] += s.x * w0 + s.y * w1 + s.z * w2 + s.w * w3;
        }
    }
    #pragma unroll
    for (int k = 0; k < 8; k++) og[g * 8 + k][h] = fmaxf(acc[k], 0.f);
    __syncthreads();
    if (t < GB * 4) {
        int b = t >> 2, o = t & 3;
        float a = 0.f;
        #pragma unroll 8
        for (int hh = 0; hh < 128; hh++) a += og[b][hh] * g_W12[(256 + hh) * 4 + o];
        g_g4[(size_t)(b0 + b) * 4 + o] = a;
    }
}

// ---------------------------------------------------------------------------
// attention kernel: one batch row per CTA.
//   x_e = relu(state2[b] @ W_intr + b_intr)   [128,128] in smem
//   score[n] = x_e[n,:] . qk[b]  (masked)  -> softmax -> alpha
//   xa = sum_n alpha[n] x_e[n,:]
//   out4 = b12 + oe4[b] + g4[b] + xa @ Wv12
// ---------------------------------------------------------------------------
#define XE_LD 129
__global__ void attn_kernel(const float* __restrict__ state2,
                            const float* __restrict__ W_intr,
                            const float* __restrict__ b_intr,
                            float* __restrict__ out, int half) {
    extern __shared__ float sm[];
    float* xe    = sm;                  // 128*129
    float* s2s   = sm + 128 * XE_LD;    // 2560
    float* qks   = s2s + 2560;          // 128
    float* alpha = qks + 128;           // 128
    float* xas   = alpha + 128;         // 128
    float* red   = xas + 128;           // 8

    int t = threadIdx.x;
    int b = blockIdx.x;

    // load state2 row block (128 x 20) + qk[b]
    const float4* src = (const float4*)(state2 + (size_t)b * 2560);
    float4* dst = (float4*)s2s;
    for (int i = t; i < 640; i += 256) dst[i] = src[i];
    if (t < 128) qks[t] = g_qk[(size_t)b * 128 + t];
    __syncthreads();

    // x_e: thread (h = t&127, n parity = t>>7) computes 64 elements, fixed h
    int h = t & 127, n0 = t >> 7;
    float w[20];
    #pragma unroll
    for (int d = 0; d < 20; d++) w[d] = W_intr[d * 128 + h];
    float bi = b_intr[h];
    for (int i = 0; i < 64; i++) {
        int n = (i << 1) | n0;
        const float4* s4 = (const float4*)(s2s + n * 20);
        float acc = bi;
        #pragma unroll
        for (int j = 0; j < 5; j++) {
            float4 a = s4[j];
            acc += a.x * w[4 * j] + a.y * w[4 * j + 1] + a.z * w[4 * j + 2] + a.w * w[4 * j + 3];
        }
        xe[n * XE_LD + h] = fmaxf(acc, 0.f);
    }
    __syncthreads();

    // score + mask (threads 0..127, one per n)
    const float NEG_INF = __int_as_float(0xff800000u);
    float sc = NEG_INF;
    bool mk = false;
    if (t < 128) {
        int n = t;
        float ms = 0.f;
        #pragma unroll
        for (int d = 0; d < 20; d++) ms += s2s[n * 20 + d];
        mk = (ms != 0.f);
        float acc = 0.f;
        #pragma unroll 8
        for (int hh = 0; hh < 128; hh++) acc += xe[n * XE_LD + hh] * qks[hh];
        sc = mk ? acc * 0.08838834764831845f : NEG_INF;  // 1/sqrt(128)
    }
    // block max over 128 scores
    float m = sc;
    #pragma unroll
    for (int off = 16; off; off >>= 1) m = fmaxf(m, __shfl_xor_sync(0xffffffffu, m, off));
    if ((t & 31) == 0 && t < 128) red[t >> 5] = m;
    __syncthreads();
    float mx = fmaxf(fmaxf(red[0], red[1]), fmaxf(red[2], red[3]));
    float e = (t < 128 && mk) ? expf(sc - mx) : 0.f;
    float s = e;
    #pragma unroll
    for (int off = 16; off; off >>= 1) s += __shfl_xor_sync(0xffffffffu, s, off);
    if ((t & 31) == 0 && t < 128) red[4 + (t >> 5)] = s;
    __syncthreads();
    float ssum = red[4] + red[5] + red[6] + red[7];
    if (t < 128) alpha[t] = (mk && ssum > 0.f) ? e / ssum : 0.f;
    __syncthreads();

    // xa[h] = sum_n alpha[n] * xe[n][h]
    if (t < 128) {
        float acc = 0.f;
        #pragma unroll 8
        for (int n = 0; n < 128; n++) acc += alpha[n] * xe[n * XE_LD + t];
        xas[t] = acc;
    }
    __syncthreads();

    // final 4 outputs
    if (t < 4) {
        int o = t;
        float a = g_b12[o] + g_oe4[(size_t)b * 4 + o] + g_g4[(size_t)b * 4 + o];
        #pragma unroll 8
        for (int hh = 0; hh < 128; hh++) a += xas[hh] * g_Wv12[hh * 4 + o];
        out[(size_t)b * 4 + o] = a;                                    // mean
        out[(size_t)half + (size_t)b * 4 + o] = fminf(fmaxf(a, -20.f), 2.f);  // log_std
    }
}

// ---------------------------------------------------------------------------
extern "C" void kernel_launch(void* const* d_in, const int* in_sizes, int n_in,
                              void* d_out, int out_size) {
    const float* state0 = (const float*)d_in[0];
    const float* state1 = (const float*)d_in[1];
    const float* state2 = (const float*)d_in[2];
    const float* W_own  = (const float*)d_in[3];
    const float* b_own  = (const float*)d_in[4];
    const float* W_intr = (const float*)d_in[5];
    const float* b_intr = (const float*)d_in[6];
    const float* W_grid = (const float*)d_in[7];
    const float* b_grid = (const float*)d_in[8];
    const float* Wq     = (const float*)d_in[9];
    const float* Wk     = (const float*)d_in[10];
    const float* Wv     = (const float*)d_in[11];
    const float* W1     = (const float*)d_in[12];
    const float* b1     = (const float*)d_in[13];
    const float* W2     = (const float*)d_in[14];
    const float* b2     = (const float*)d_in[15];
    float* out = (float*)d_out;

    const int ATTN_SMEM = (128 * XE_LD + 2560 + 128 * 3 + 8) * (int)sizeof(float);
    cudaFuncSetAttribute(attn_kernel, cudaFuncAttributeMaxDynamicSharedMemorySize, ATTN_SMEM);

    prep1_kernel<<<64, 256>>>(Wq, Wk, W1, b1, W2, b2);
    prep2_kernel<<<2, 256>>>(Wv);
    own_kernel<<<B_SZ / OB, 256>>>(state0, W_own, b_own);
    grid_kernel<<<B_SZ / GB, 256>>>(state1, W_grid, b_grid);
    attn_kernel<<<B_SZ, 256, ATTN_SMEM>>>(state2, W_intr, b_intr, out, out_size / 2);
}

// round 11
// speedup vs baseline: 1.0150x; 1.0150x over previous
#include <cuda_runtime.h>
#include <cuda_bf16.h>
#include <math.h>

// Problem constants
#define B_SZ 8192
#define N_SZ 128
#define D_OWN 16
#define D_GRID 512
#define D_INTR 20
#define H_SZ 128

// Folded-weight + intermediate scratch (device globals: allocation-free)
__device__ float g_Wqk[128 * 128];   // Wq @ Wk^T
__device__ float g_W12[384 * 4];     // W1 @ W2
__device__ float g_Wv12[128 * 4];    // Wv @ W12[128:256]
__device__ float g_b12[4];           // b1 @ W2 + b2
__device__ float g_qk[B_SZ * 128];   // per-batch attention query folded through Wk
__device__ float g_oe4[B_SZ * 4];    // own_e contribution to output
__device__ float g_g4[B_SZ * 4];     // own_grid contribution to output

// ---------------------------------------------------------------------------
// prep1: fold Wqk = Wq @ Wk^T, W12 = W1 @ W2, b12 = b1 @ W2 + b2
// ---------------------------------------------------------------------------
__global__ void prep1_kernel(const float* __restrict__ Wq,
                             const float* __restrict__ Wk,
                             const float* __restrict__ W1,
                             const float* __restrict__ b1,
                             const float* __restrict__ W2,
                             const float* __restrict__ b2) {
    int t = blockIdx.x * blockDim.x + threadIdx.x;
    if (t < 16384) {
        int hp = t >> 7, d = t & 127;
        float acc = 0.f;
        #pragma unroll 8
        for (int h = 0; h < 128; h++) acc += Wq[hp * 128 + h] * Wk[d * 128 + h];
        g_Wqk[t] = acc;  // [hp][d]
    }
    if (t < 1536) {
        int i = t >> 2, o = t & 3;
        float acc = 0.f;
        #pragma unroll 8
        for (int j = 0; j < 128; j++) acc += W1[i * 128 + j] * W2[j * 4 + o];
        g_W12[t] = acc;
    }
    if (t < 4) {
        float acc = b2[t];
        for (int j = 0; j < 128; j++) acc += b1[j] * W2[j * 4 + t];
        g_b12[t] = acc;
    }
}

// ---------------------------------------------------------------------------
// prep2: Wv12 = Wv @ W12[128:256]  (needs g_W12 -> separate launch)
// ---------------------------------------------------------------------------
__global__ void prep2_kernel(const float* __restrict__ Wv) {
    int t = blockIdx.x * blockDim.x + threadIdx.x;
    if (t < 512) {
        int h = t >> 2, o = t & 3;
        float acc = 0.f;
        #pragma unroll 8
        for (int i = 0; i < 128; i++) acc += Wv[h * 128 + i] * g_W12[(128 + i) * 4 + o];
        g_Wv12[t] = acc;
    }
}

// ---------------------------------------------------------------------------
// own path: own_e = relu(state0 @ W_own + b_own)
//           qk[b] = own_e @ Wqk ; oe4[b] = own_e @ W12[0:128]
// 8 batch rows per CTA to amortize Wqk traffic.
// ---------------------------------------------------------------------------
#define OB 8
__global__ void own_kernel(const float* __restrict__ state0,
                           const float* __restrict__ W_own,
                           const float* __restrict__ b_own) {
    __shared__ float s0[OB * 16];
    __shared__ float oe[OB][128];
    int t = threadIdx.x;
    int b0 = blockIdx.x * OB;
    if (t < OB * 16) s0[t] = state0[b0 * 16 + t];
    __syncthreads();
    #pragma unroll
    for (int k = 0; k < 4; k++) {
        int idx = t + k * 256;
        int b = idx >> 7, h = idx & 127;
        float acc = b_own[h];
        #pragma unroll
        for (int d = 0; d < 16; d++) acc += s0[b * 16 + d] * W_own[d * 128 + h];
        oe[b][h] = fmaxf(acc, 0.f);
    }
    __syncthreads();
    // qk: thread (d = t&127, half = t>>7) handles 4 batch rows
    int d = t & 127, g = t >> 7;
    float a0 = 0.f, a1 = 0.f, a2 = 0.f, a3 = 0.f;
    #pragma unroll 4
    for (int h = 0; h < 128; h++) {
        float w = g_Wqk[h * 128 + d];
        a0 += oe[g * 4 + 0][h] * w;
        a1 += oe[g * 4 + 1][h] * w;
        a2 += oe[g * 4 + 2][h] * w;
        a3 += oe[g * 4 + 3][h] * w;
    }
    g_qk[(size_t)(b0 + g * 4 + 0) * 128 + d] = a0;
    g_qk[(size_t)(b0 + g * 4 + 1) * 128 + d] = a1;
    g_qk[(size_t)(b0 + g * 4 + 2) * 128 + d] = a2;
    g_qk[(size_t)(b0 + g * 4 + 3) * 128 + d] = a3;
    if (t < OB * 4) {
        int b = t >> 2, o = t & 3;
        float a = 0.f;
        #pragma unroll 8
        for (int h = 0; h < 128; h++) a += oe[b][h] * g_W12[h * 4 + o];
        g_oe4[(size_t)(b0 + b) * 4 + o] = a;
    }
}

// ---------------------------------------------------------------------------
// grid path: own_grid = relu(state1 @ W_grid + b_grid); g4 = own_grid @ W12[256:384]
// 16 batch rows per CTA so W_grid (256 KB) is streamed 512x not 8192x.
// ---------------------------------------------------------------------------
#define GB 16
__global__ void grid_kernel(const float* __restrict__ state1,
                            const float* __restrict__ W_grid,
                            const float* __restrict__ b_grid) {
    __shared__ float4 s1[GB * 128];   // 16 rows x 512 floats = 32KB
    __shared__ float og[GB][128];
    int t = threadIdx.x;
    int b0 = blockIdx.x * GB;
    const float4* src = (const float4*)(state1 + (size_t)b0 * 512);
    for (int i = t; i < GB * 128; i += 256) s1[i] = src[i];
    __syncthreads();
    int h = t & 127, g = t >> 7;  // each (h, g) handles 8 rows
    float acc[8];
    float bg = b_grid[h];
    #pragma unroll
    for (int k = 0; k < 8; k++) acc[k] = bg;
    for (int dc = 0; dc < 128; dc++) {
        float w0 = W_grid[(4 * dc + 0) * 128 + h];
        float w1 = W_grid[(4 * dc + 1) * 128 + h];
        float w2 = W_grid[(4 * dc + 2) * 128 + h];
        float w3 = W_grid[(4 * dc + 3) * 128 + h];
        #pragma unroll
        for (int k = 0; k < 8; k++) {
            float4 s = s1[(g * 8 + k) * 128 + dc];
            acc[k] += s.x * w0 + s.y * w1 + s.z * w2 + s.w * w3;
        }
    }
    #pragma unroll
    for (int k = 0; k < 8; k++) og[g * 8 + k][h] = fmaxf(acc[k], 0.f);
    __syncthreads();
    if (t < GB * 4) {
        int b = t >> 2, o = t & 3;
        float a = 0.f;
        #pragma unroll 8
        for (int hh = 0; hh < 128; hh++) a += og[b][hh] * g_W12[(256 + hh) * 4 + o];
        g_g4[(size_t)(b0 + b) * 4 + o] = a;
    }
}

// ---------------------------------------------------------------------------
// attention kernel: one batch row per CTA.
//   x_e = relu(state2[b] @ W_intr + b_intr)   [128,128] in smem
//   score[n] = x_e[n,:] . qk[b]  (masked)  -> softmax -> alpha
//   xa = sum_n alpha[n] x_e[n,:]
//   out4 = b12 + oe4[b] + g4[b] + xa @ Wv12
// ---------------------------------------------------------------------------
#define XE_LD 129
__global__ void attn_kernel(const float* __restrict__ state2,
                            const float* __restrict__ W_intr,
                            const float* __restrict__ b_intr,
                            float* __restrict__ out, int half) {
    extern __shared__ float sm[];
    float* xe    = sm;                  // 128*129
    float* s2s   = sm + 128 * XE_LD;    // 2560
    float* qks   = s2s + 2560;          // 128
    float* alpha = qks + 128;           // 128
    float* xas   = alpha + 128;         // 128
    float* red   = xas + 128;           // 8

    int t = threadIdx.x;
    int b = blockIdx.x;

    // load state2 row block (128 x 20) + qk[b]
    const float4* src = (const float4*)(state2 + (size_t)b * 2560);
    float4* dst = (float4*)s2s;
    for (int i = t; i < 640; i += 256) dst[i] = src[i];
    if (t < 128) qks[t] = g_qk[(size_t)b * 128 + t];
    __syncthreads();

    // x_e: thread (h = t&127, n parity = t>>7) computes 64 elements, fixed h
    int h = t & 127, n0 = t >> 7;
    float w[20];
    #pragma unroll
    for (int d = 0; d < 20; d++) w[d] = W_intr[d * 128 + h];
    float bi = b_intr[h];
    for (int i = 0; i < 64; i++) {
        int n = (i << 1) | n0;
        const float4* s4 = (const float4*)(s2s + n * 20);
        float acc = bi;
        #pragma unroll
        for (int j = 0; j < 5; j++) {
            float4 a = s4[j];
            acc += a.x * w[4 * j] + a.y * w[4 * j + 1] + a.z * w[4 * j + 2] + a.w * w[4 * j + 3];
        }
        xe[n * XE_LD + h] = fmaxf(acc, 0.f);
    }
    __syncthreads();

    // score + mask (threads 0..127, one per n)
    const float NEG_INF = __int_as_float(0xff800000u);
    float sc = NEG_INF;
    bool mk = false;
    if (t < 128) {
        int n = t;
        float ms = 0.f;
        #pragma unroll
        for (int d = 0; d < 20; d++) ms += s2s[n * 20 + d];
        mk = (ms != 0.f);
        float acc = 0.f;
        #pragma unroll 8
        for (int hh = 0; hh < 128; hh++) acc += xe[n * XE_LD + hh] * qks[hh];
        sc = mk ? acc * 0.08838834764831845f : NEG_INF;  // 1/sqrt(128)
    }
    // block max over 128 scores
    float m = sc;
    #pragma unroll
    for (int off = 16; off; off >>= 1) m = fmaxf(m, __shfl_xor_sync(0xffffffffu, m, off));
    if ((t & 31) == 0 && t < 128) red[t >> 5] = m;
    __syncthreads();
    float mx = fmaxf(fmaxf(red[0], red[1]), fmaxf(red[2], red[3]));
    float e = (t < 128 && mk) ? expf(sc - mx) : 0.f;
    float s = e;
    #pragma unroll
    for (int off = 16; off; off >>= 1) s += __shfl_xor_sync(0xffffffffu, s, off);
    if ((t & 31) == 0 && t < 128) red[4 + (t >> 5)] = s;
    __syncthreads();
    float ssum = red[4] + red[5] + red[6] + red[7];
    if (t < 128) alpha[t] = (mk && ssum > 0.f) ? e / ssum : 0.f;
    __syncthreads();

    // xa[h] = sum_n alpha[n] * xe[n][h]
    if (t < 128) {
        float acc = 0.f;
        #pragma unroll 8
        for (int n = 0; n < 128; n++) acc += alpha[n] * xe[n * XE_LD + t];
        xas[t] = acc;
    }
    __syncthreads();

    // final 4 outputs
    if (t < 4) {
        int o = t;
        float a = g_b12[o] + g_oe4[(size_t)b * 4 + o] + g_g4[(size_t)b * 4 + o];
        #pragma unroll 8
        for (int hh = 0; hh < 128; hh++) a += xas[hh] * g_Wv12[hh * 4 + o];
        out[(size_t)b * 4 + o] = a;                                    // mean
        out[(size_t)half + (size_t)b * 4 + o] = fminf(fmaxf(a, -20.f), 2.f);  // log_std
    }
}

// ---------------------------------------------------------------------------
extern "C" void kernel_launch(void* const* d_in, const int* in_sizes, int n_in,
                              void* d_out, int out_size) {
    const float* state0 = (const float*)d_in[0];
    const float* state1 = (const float*)d_in[1];
    const float* state2 = (const float*)d_in[2];
    const float* W_own  = (const float*)d_in[3];
    const float* b_own  = (const float*)d_in[4];
    const float* W_intr = (const float*)d_in[5];
    const float* b_intr = (const float*)d_in[6];
    const float* W_grid = (const float*)d_in[7];
    const float* b_grid = (const float*)d_in[8];
    const float* Wq     = (const float*)d_in[9];
    const float* Wk     = (const float*)d_in[10];
    const float* Wv     = (const float*)d_in[11];
    const float* W1     = (const float*)d_in[12];
    const float* b1     = (const float*)d_in[13];
    const float* W2     = (const float*)d_in[14];
    const float* b2     = (const float*)d_in[15];
    float* out = (float*)d_out;

    const int ATTN_SMEM = (128 * XE_LD + 2560 + 128 * 3 + 8) * (int)sizeof(float);
    cudaFuncSetAttribute(attn_kernel, cudaFuncAttributeMaxDynamicSharedMemorySize, ATTN_SMEM);

    prep1_kernel<<<64, 256>>>(Wq, Wk, W1, b1, W2, b2);
    prep2_kernel<<<2, 256>>>(Wv);
    own_kernel<<<B_SZ / OB, 256>>>(state0, W_own, b_own);
    grid_kernel<<<B_SZ / GB, 256>>>(state1, W_grid, b_grid);
    attn_kernel<<<B_SZ, 256, ATTN_SMEM>>>(state2, W_intr, b_intr, out, out_size / 2);
}